// round 13
// baseline (speedup 1.0000x reference)
#include <cuda_runtime.h>
#include <cuda_fp16.h>
#include <math.h>
#include <cstdint>

// Problem constants
#define BB 2
#define SS 2048
#define EE 1024
#define HH 16
#define DHH 64
#define MM (BB * SS)   // 4096

// ---------------------------------------------------------------------------
// Scratch (allocation-free rule: __device__ globals)
// ---------------------------------------------------------------------------
__device__ __half g_hQ[MM * EE];     // projected Q (prescaled by log2e/sqrt(S))
__device__ __half g_hK[MM * EE];
__device__ __half g_hV[MM * EE];
__device__ __half g_hC[MM * EE];     // attention context
__device__ __half g_hXq[MM * EE];    // fp16 copies of inputs
__device__ __half g_hXk[MM * EE];
__device__ __half g_hXv[MM * EE];
__device__ __half g_hWq[EE * EE];    // fp16 copies of weights
__device__ __half g_hWk[EE * EE];
__device__ __half g_hWv[EE * EE];
__device__ __half g_hWo[EE * EE];
__device__ __half g_hM[BB * SS];     // mask as fp16

// ---------------------------------------------------------------------------
// Helpers (baseline PTX only: sm_80-class mma/ldmatrix/cp.async)
// ---------------------------------------------------------------------------
__device__ __forceinline__ uint32_t smem_u32(const void* p) {
    uint32_t a;
    asm("{ .reg .u64 t; cvta.to.shared.u64 t, %1; cvt.u32.u64 %0, t; }"
        : "=r"(a) : "l"(p));
    return a;
}
__device__ __forceinline__ void ldsm4(uint32_t* r, uint32_t a) {
    asm volatile("ldmatrix.sync.aligned.m8n8.x4.shared.b16 {%0,%1,%2,%3}, [%4];"
        : "=r"(r[0]), "=r"(r[1]), "=r"(r[2]), "=r"(r[3]) : "r"(a));
}
__device__ __forceinline__ void ldsm4t(uint32_t* r, uint32_t a) {
    asm volatile("ldmatrix.sync.aligned.m8n8.x4.trans.shared.b16 {%0,%1,%2,%3}, [%4];"
        : "=r"(r[0]), "=r"(r[1]), "=r"(r[2]), "=r"(r[3]) : "r"(a));
}
// f32-accumulate HMMA
__device__ __forceinline__ void mma16816(float* c, const uint32_t* a, const uint32_t* b) {
    asm volatile("mma.sync.aligned.m16n8k16.row.col.f32.f16.f16.f32 "
        "{%0,%1,%2,%3}, {%4,%5,%6,%7}, {%8,%9}, {%0,%1,%2,%3};"
        : "+f"(c[0]), "+f"(c[1]), "+f"(c[2]), "+f"(c[3])
        : "r"(a[0]), "r"(a[1]), "r"(a[2]), "r"(a[3]), "r"(b[0]), "r"(b[1]));
}
// f16-accumulate HMMA (2x rate)
__device__ __forceinline__ void mma16816h(uint32_t* c, const uint32_t* a, const uint32_t* b) {
    asm volatile("mma.sync.aligned.m16n8k16.row.col.f16.f16.f16.f16 "
        "{%0,%1}, {%2,%3,%4,%5}, {%6,%7}, {%0,%1};"
        : "+r"(c[0]), "+r"(c[1])
        : "r"(a[0]), "r"(a[1]), "r"(a[2]), "r"(a[3]), "r"(b[0]), "r"(b[1]));
}
__device__ __forceinline__ uint32_t pack2(float x, float y) {
    __half2 h = __floats2half2_rn(x, y);
    return *reinterpret_cast<uint32_t*>(&h);
}
__device__ __forceinline__ uint32_t h2ex2(uint32_t x) {
    uint32_t y;
    asm("ex2.approx.f16x2 %0, %1;" : "=r"(y) : "r"(x));
    return y;
}
__device__ __forceinline__ uint32_t h2mul(uint32_t a, uint32_t b) {
    uint32_t y;
    asm("mul.f16x2 %0, %1, %2;" : "=r"(y) : "r"(a), "r"(b));
    return y;
}
__device__ __forceinline__ void cpa16(uint32_t s, const void* g) {
    asm volatile("cp.async.cg.shared.global [%0], [%1], 16;" :: "r"(s), "l"(g));
}
#define CP_COMMIT() asm volatile("cp.async.commit_group;" ::: "memory")
#define CP_WAIT0()  asm volatile("cp.async.wait_group 0;"  ::: "memory")
#define CP_WAIT2()  asm volatile("cp.async.wait_group 2;"  ::: "memory")

// Swizzles
__device__ __forceinline__ uint32_t sw64(int row, int ch) {
    return (uint32_t)(row * 64 + ((ch ^ ((row >> 1) & 3)) << 4));
}
__device__ __forceinline__ uint32_t sw128(int row, int ch) {
    uint32_t b = (uint32_t)(row * 128 + ch * 16);
    return b ^ ((b >> 3) & 0x70);
}
__device__ __forceinline__ uint32_t offA64(int rb, int cb, int lane) {
    int li = lane & 7, m = lane >> 3;
    return sw64(rb + li + (m & 1) * 8, cb + (m >> 1));
}
__device__ __forceinline__ uint32_t offB64(int rb, int cb, int lane) {
    int li = lane & 7, m = lane >> 3;
    return sw64(rb + (m >> 1) * 8 + li, cb + (m & 1));
}
__device__ __forceinline__ uint32_t offA128(int rb, int cb, int lane) {
    int li = lane & 7, m = lane >> 3;
    return sw128(rb + li + (m & 1) * 8, cb + (m >> 1));
}
__device__ __forceinline__ uint32_t offB128(int rb, int cb, int lane) {
    int li = lane & 7, m = lane >> 3;
    return sw128(rb + (m >> 1) * 8 + li, cb + (m & 1));
}

// ---------------------------------------------------------------------------
// Batched fp32 -> fp16 convert: 7 tensors + mask in ONE launch.
// ---------------------------------------------------------------------------
struct CvtArgs { const float4* s[7]; uint2* d[7]; const int4* ms; uint2* dM; };
#define ACT4 1048576
#define W4   262144
#define CVT_MAIN (3 * ACT4 + 4 * W4)

__global__ __launch_bounds__(256) void cvt_all(CvtArgs a)
{
    int i = blockIdx.x * 256 + threadIdx.x;
    if (i < CVT_MAIN) {
        int seg, off;
        if (i < 3 * ACT4) { seg = i >> 20;               off = i & (ACT4 - 1); }
        else              { int j = i - 3 * ACT4;
                            seg = 3 + (j >> 18);         off = j & (W4 - 1); }
        float4 v = a.s[seg][off];
        uint2 o;
        o.x = pack2(v.x, v.y);
        o.y = pack2(v.z, v.w);
        a.d[seg][off] = o;
    } else {
        int j = i - CVT_MAIN;                 // [0, 1024): mask int4 -> half x4
        int4 m = a.ms[j];
        uint2 o;
        o.x = pack2((float)m.x, (float)m.y);
        o.y = pack2((float)m.z, (float)m.w);
        a.dM[j] = o;
    }
}

// ---------------------------------------------------------------------------
// fp16 GEMM body — R11's 4-stage cp.async pipeline (UNCHANGED, proven).
// ---------------------------------------------------------------------------
#define G_STAGE 16384u
#define G_SMEM  65536

template<bool OUT_HALF, bool HAS_BIAS>
__device__ __forceinline__ void gemm_body(
    const __half* __restrict__ A, const __half* __restrict__ B,
    const float* __restrict__ bias, void* __restrict__ Cout,
    int M, int N, float scale, char* smem)
{
    const int K = EE, NKB = 32;
    const int tid = threadIdx.x, lane = tid & 31, wid = tid >> 5;
    const int wm = wid & 3, wn = wid >> 2;
    const int bm = blockIdx.y * 128, bn = blockIdx.x * 128;

    const __half* Ag = A + (size_t)bm * K;
    const __half* Bg = B + (size_t)bn * K;
    const uint32_t sS = smem_u32(smem);

    float acc[2][8][4];
#pragma unroll
    for (int i = 0; i < 2; i++)
#pragma unroll
        for (int j = 0; j < 8; j++)
#pragma unroll
            for (int x = 0; x < 4; x++) acc[i][j][x] = 0.f;

    auto issue = [&](int kb, int st) {
        const uint32_t dA = sS + (uint32_t)st * G_STAGE;
#pragma unroll
        for (int i = 0; i < 2; i++) {
            int s = tid + 256 * i;
            int row = s >> 2, ch = s & 3;
            cpa16(dA + sw64(row, ch),         Ag + (size_t)row * K + kb * 32 + ch * 8);
            cpa16(dA + 8192u + sw64(row, ch), Bg + (size_t)row * K + kb * 32 + ch * 8);
        }
        CP_COMMIT();
    };

    issue(0, 0); issue(1, 1); issue(2, 2);

    auto kblock = [&](int kb, int st) {
        const uint32_t stA = sS + (uint32_t)st * G_STAGE;
        const uint32_t stB = stA + 8192u;
        CP_WAIT2();
        __syncthreads();

        uint32_t ac[2][4], an[2][4], bb[2][4];
        ldsm4(ac[0], stA + offA64(wm * 32,      0, lane));
        ldsm4(ac[1], stA + offA64(wm * 32 + 16, 0, lane));
        ldsm4(bb[0], stB + offB64(wn * 64, 0, lane));

        if (kb + 3 < NKB) issue(kb + 3, (kb + 3) & 3);
        else CP_COMMIT();   // empty group keeps wait_group 2 semantics uniform

#pragma unroll
        for (int kt = 0; kt < 2; kt++) {
#pragma unroll
            for (int np = 0; np < 4; np++) {
                const int nx = kt * 4 + np + 1;      // next fragment index
                if (nx < 8)
                    ldsm4(bb[(np + 1) & 1],
                          stB + offB64(wn * 64 + (nx & 3) * 16, (nx >> 2) * 2, lane));
                if (kt == 0 && np == 2)
                    ldsm4(an[0], stA + offA64(wm * 32,      2, lane));
                if (kt == 0 && np == 3)
                    ldsm4(an[1], stA + offA64(wm * 32 + 16, 2, lane));
                const uint32_t* a0 = kt ? an[0] : ac[0];
                const uint32_t* a1 = kt ? an[1] : ac[1];
                const uint32_t* bf = bb[np & 1];
                mma16816(acc[0][2 * np],     a0, bf);
                mma16816(acc[0][2 * np + 1], a0, bf + 2);
                mma16816(acc[1][2 * np],     a1, bf);
                mma16816(acc[1][2 * np + 1], a1, bf + 2);
            }
        }
    };

#pragma unroll 1
    for (int kb4 = 0; kb4 < NKB; kb4 += 4) {
        kblock(kb4 + 0, 0);
        kblock(kb4 + 1, 1);
        kblock(kb4 + 2, 2);
        kblock(kb4 + 3, 3);
    }

    const int g = lane >> 2, t = lane & 3;
#pragma unroll
    for (int mt = 0; mt < 2; mt++) {
        const int row0 = bm + wm * 32 + mt * 16 + g;
#pragma unroll
        for (int nt = 0; nt < 8; nt++) {
            const int col = bn + wn * 64 + nt * 8 + 2 * t;
            float* c = acc[mt][nt];
            if constexpr (OUT_HALF) {
                __half* O = (__half*)Cout;
                *(uint32_t*)(O + (size_t)row0 * N + col) =
                    pack2(c[0] * scale, c[1] * scale);
                *(uint32_t*)(O + (size_t)(row0 + 8) * N + col) =
                    pack2(c[2] * scale, c[3] * scale);
            } else {
                float* O = (float*)Cout;
                const float b0 = HAS_BIAS ? bias[col] : 0.f;
                const float b1 = HAS_BIAS ? bias[col + 1] : 0.f;
                *(float2*)(O + (size_t)row0 * N + col) =
                    make_float2(c[0] + b0, c[1] + b1);
                *(float2*)(O + (size_t)(row0 + 8) * N + col) =
                    make_float2(c[2] + b0, c[3] + b1);
            }
        }
    }
}

struct QkvArgs {
    const __half* A[3];
    const __half* B[3];
    __half*       C[3];
    float         scale[3];
};

__global__ __launch_bounds__(256, 2) void gemm_qkv(QkvArgs p)
{
    extern __shared__ __align__(16) char gsm[];
    const int z = blockIdx.z;
    gemm_body<true, false>(p.A[z], p.B[z], nullptr, p.C[z],
                           MM, EE, p.scale[z], gsm);
}

__global__ __launch_bounds__(256, 2) void gemm_out(
    const __half* __restrict__ A, const __half* __restrict__ B,
    const float* __restrict__ bias, float* __restrict__ C)
{
    extern __shared__ __align__(16) char gsm[];
    gemm_body<false, true>(A, B, bias, C, MM, EE, 1.0f, gsm);
}

// ---------------------------------------------------------------------------
// Flash attention v7: BQ=256 (8 warps x 32 q-rows), BKV=64, DH=64.
// Per-warp body IDENTICAL to R11's proven flash4 (persistent Q frags,
// joint-qb S with shared K frags, in-place f16x2 softmax, ones-MMA row sums).
// Grid = 256 CTAs <= 304 slots (2 CTAs/SM) -> SINGLE WAVE; KV stream read
// by 8 CTAs/(b,h) instead of 16 -> half the L2 KV traffic.
// smem: Q 32K | K0 8K | K1 8K | V0 8K | V1 8K | mask 256B  = 64.3 KB
// ---------------------------------------------------------------------------
#define F_OQ  0u
#define F_OK(i) (32768u + (i) * 8192u)
#define F_OV(i) (49152u + (i) * 8192u)
#define F_OMK   65536u
#define F_SMEM  (65536 + 2 * 128)

__global__ __launch_bounds__(256, 2) void flash7(
    const __half* __restrict__ Qh, const __half* __restrict__ Kh,
    const __half* __restrict__ Vh, const __half* __restrict__ Mh,
    __half* __restrict__ Oh)
{
    extern __shared__ __align__(16) char smraw[];
    const uint32_t S = smem_u32(smraw);

    const int tid = threadIdx.x, lane = tid & 31, w = tid >> 5;   // w: 0..7
    const int q0 = blockIdx.x * 256, h = blockIdx.y, b = blockIdx.z;
    const int g = lane >> 2, t = lane & 3;

    const __half* Qg = Qh + ((size_t)(b * SS + q0)) * EE + h * DHH;
    const __half* Kg = Kh + ((size_t)b * SS) * EE + h * DHH;
    const __half* Vg = Vh + ((size_t)b * SS) * EE + h * DHH;
    const __half* mgh = Mh + b * SS;

    auto issue_kv = [&](int kv0, int bi) {
#pragma unroll
        for (int i = 0; i < 2; i++) {
            int s = tid + 256 * i;
            int row = s >> 3, ch = s & 7;
            cpa16(S + F_OK(bi) + sw128(row, ch),
                  Kg + (size_t)(kv0 + row) * EE + ch * 8);
            cpa16(S + F_OV(bi) + sw128(row, ch),
                  Vg + (size_t)(kv0 + row) * EE + ch * 8);
        }
        if (tid < 8)
            cpa16(S + F_OMK + bi * 128 + tid * 16, mgh + kv0 + tid * 8);
        CP_COMMIT();
    };

    // prologue: Q tile (256 rows) + KV tile 0 in one group
#pragma unroll
    for (int i = 0; i < 8; i++) {
        int s = tid + 256 * i;
        int row = s >> 3, ch = s & 7;
        cpa16(S + F_OQ + sw128(row, ch), Qg + (size_t)row * EE + ch * 8);
    }
    issue_kv(0, 0);

    uint32_t aq[2][4][4];
    float acc[2][8][4];
    float lacc[2][4];
#pragma unroll
    for (int qb = 0; qb < 2; qb++) {
#pragma unroll
        for (int j = 0; j < 8; j++)
#pragma unroll
            for (int x = 0; x < 4; x++) acc[qb][j][x] = 0.f;
#pragma unroll
        for (int x = 0; x < 4; x++) lacc[qb][x] = 0.f;
    }
    const uint32_t ONES[2] = { 0x3C003C00u, 0x3C003C00u };  // half2(1,1)

    const int NT = SS / 64;
    for (int it = 0; it < NT; it++) {
        const int cur = it & 1;
        CP_WAIT0();
        __syncthreads();
        if (it == 0) {
#pragma unroll
            for (int qb = 0; qb < 2; qb++)
#pragma unroll
                for (int kt = 0; kt < 4; kt++)
                    ldsm4(aq[qb][kt], S + F_OQ + offA128(w * 32 + qb * 16, kt * 2, lane));
        }
        if (it + 1 < NT) issue_kv((it + 1) * 64, cur ^ 1);

        // ---- S = Q K^T, fp16 accumulate, joint q-blocks (K frag shared) ----
        uint32_t sh[2][8][2];
#pragma unroll
        for (int qb = 0; qb < 2; qb++)
#pragma unroll
            for (int j = 0; j < 8; j++) { sh[qb][j][0] = 0u; sh[qb][j][1] = 0u; }
#pragma unroll
        for (int kt = 0; kt < 4; kt++)
#pragma unroll
            for (int np = 0; np < 4; np++) {
                uint32_t bf[4];
                ldsm4(bf, S + F_OK(cur) + offB128(np * 16, kt * 2, lane));
                mma16816h(sh[0][2 * np],     aq[0][kt], bf);
                mma16816h(sh[0][2 * np + 1], aq[0][kt], bf + 2);
                mma16816h(sh[1][2 * np],     aq[1][kt], bf);
                mma16816h(sh[1][2 * np + 1], aq[1][kt], bf + 2);
            }

        // ---- P = exp2(S) * mask, f16x2, in place ----
#pragma unroll
        for (int j = 0; j < 8; j++) {
            const uint32_t mhj =
                *(const uint32_t*)(smraw + F_OMK + cur * 128 + (j * 8 + 2 * t) * 2);
            sh[0][j][0] = h2mul(h2ex2(sh[0][j][0]), mhj);
            sh[0][j][1] = h2mul(h2ex2(sh[0][j][1]), mhj);
            sh[1][j][0] = h2mul(h2ex2(sh[1][j][0]), mhj);
            sh[1][j][1] = h2mul(h2ex2(sh[1][j][1]), mhj);
        }

        // ---- O += P V (f32 accum) ; l += P * ones ----
#pragma unroll
        for (int kt = 0; kt < 4; kt++) {
            uint32_t ap0[4] = { sh[0][2 * kt][0], sh[0][2 * kt][1],
                                sh[0][2 * kt + 1][0], sh[0][2 * kt + 1][1] };
            uint32_t ap1[4] = { sh[1][2 * kt][0], sh[1][2 * kt][1],
                                sh[1][2 * kt + 1][0], sh[1][2 * kt + 1][1] };
            mma16816(lacc[0], ap0, ONES);
            mma16816(lacc[1], ap1, ONES);
#pragma unroll
            for (int np = 0; np < 4; np++) {
                uint32_t vf[4];
                ldsm4t(vf, S + F_OV(cur) + offA128(kt * 16, np * 2, lane));
                mma16816(acc[0][2 * np],     ap0, vf);
                mma16816(acc[0][2 * np + 1], ap0, vf + 2);
                mma16816(acc[1][2 * np],     ap1, vf);
                mma16816(acc[1][2 * np + 1], ap1, vf + 2);
            }
        }
        // no bottom sync: next iteration's top barrier provides ordering
    }

    // normalize and store
#pragma unroll
    for (int qb = 0; qb < 2; qb++) {
        const float i0 = 1.f / lacc[qb][0];
        const float i1 = 1.f / lacc[qb][2];
        __half* O0 = Oh + ((size_t)(b * SS + q0 + w * 32 + qb * 16 + g)) * EE + h * DHH;
        __half* O1 = O0 + 8 * EE;
#pragma unroll
        for (int j = 0; j < 8; j++) {
            const int col = j * 8 + 2 * t;
            *(uint32_t*)(O0 + col) = pack2(acc[qb][j][0] * i0, acc[qb][j][1] * i0);
            *(uint32_t*)(O1 + col) = pack2(acc[qb][j][2] * i1, acc[qb][j][3] * i1);
        }
    }
}

// ---------------------------------------------------------------------------
// Launch: 4 kernels total
// ---------------------------------------------------------------------------
extern "C" void kernel_launch(void* const* d_in, const int* in_sizes, int n_in,
                              void* d_out, int out_size)
{
    const float* q    = (const float*)d_in[0];
    const float* k    = (const float*)d_in[1];
    const float* v    = (const float*)d_in[2];
    const int*   mask = (const int*)d_in[3];
    const float* Wq   = (const float*)d_in[4];
    const float* Wk   = (const float*)d_in[5];
    const float* Wv   = (const float*)d_in[6];
    const float* Wo   = (const float*)d_in[7];
    const float* bo   = (const float*)d_in[8];
    float* out = (float*)d_out;

    __half *hQ, *hK, *hV, *hC, *hXq, *hXk, *hXv, *hWq, *hWk, *hWv, *hWo, *hM;
    cudaGetSymbolAddress((void**)&hQ,  g_hQ);
    cudaGetSymbolAddress((void**)&hK,  g_hK);
    cudaGetSymbolAddress((void**)&hV,  g_hV);
    cudaGetSymbolAddress((void**)&hC,  g_hC);
    cudaGetSymbolAddress((void**)&hXq, g_hXq);
    cudaGetSymbolAddress((void**)&hXk, g_hXk);
    cudaGetSymbolAddress((void**)&hXv, g_hXv);
    cudaGetSymbolAddress((void**)&hWq, g_hWq);
    cudaGetSymbolAddress((void**)&hWk, g_hWk);
    cudaGetSymbolAddress((void**)&hWv, g_hWv);
    cudaGetSymbolAddress((void**)&hWo, g_hWo);
    cudaGetSymbolAddress((void**)&hM,  g_hM);

    // 1) all fp32->fp16 converts (+ mask int->fp16) in one launch
    CvtArgs ca;
    ca.s[0] = (const float4*)q;  ca.d[0] = (uint2*)hXq;
    ca.s[1] = (const float4*)k;  ca.d[1] = (uint2*)hXk;
    ca.s[2] = (const float4*)v;  ca.d[2] = (uint2*)hXv;
    ca.s[3] = (const float4*)Wq; ca.d[3] = (uint2*)hWq;
    ca.s[4] = (const float4*)Wk; ca.d[4] = (uint2*)hWk;
    ca.s[5] = (const float4*)Wv; ca.d[5] = (uint2*)hWv;
    ca.s[6] = (const float4*)Wo; ca.d[6] = (uint2*)hWo;
    ca.ms = (const int4*)mask;   ca.dM = (uint2*)hM;
    cvt_all<<<CVT_MAIN / 256 + 4, 256>>>(ca);

    // 2) QKV projections, one launch (grid.z = 3), 4-stage pipelined GEMM
    cudaFuncSetAttribute(gemm_qkv, cudaFuncAttributeMaxDynamicSharedMemorySize,
                         G_SMEM);
    cudaFuncSetAttribute(gemm_out, cudaFuncAttributeMaxDynamicSharedMemorySize,
                         G_SMEM);
    QkvArgs pa;
    pa.A[0] = hXq; pa.B[0] = hWq; pa.C[0] = hQ; pa.scale[0] = 0.03188010863008193f;
    pa.A[1] = hXk; pa.B[1] = hWk; pa.C[1] = hK; pa.scale[1] = 1.0f;
    pa.A[2] = hXv; pa.B[2] = hWv; pa.C[2] = hV; pa.scale[2] = 1.0f;
    dim3 gqkv(EE / 128, MM / 128, 3);
    gemm_qkv<<<gqkv, 256, G_SMEM>>>(pa);

    // 3) attention: 256 CTAs (8 per b,h), 8 warps, single wave
    cudaFuncSetAttribute(flash7, cudaFuncAttributeMaxDynamicSharedMemorySize,
                         F_SMEM);
    flash7<<<dim3(SS / 256, HH, BB), 256, F_SMEM>>>(hQ, hK, hV, hM, hC);

    // 4) output projection + bias
    dim3 gg(EE / 128, MM / 128);
    gemm_out<<<gg, 256, G_SMEM>>>(hC, hWo, bo, out);
}

// round 14
// speedup vs baseline: 1.1433x; 1.1433x over previous
#include <cuda_runtime.h>
#include <cuda_fp16.h>
#include <math.h>
#include <cstdint>

// Problem constants
#define BB 2
#define SS 2048
#define EE 1024
#define HH 16
#define DHH 64
#define MM (BB * SS)   // 4096

// ---------------------------------------------------------------------------
// Scratch (allocation-free rule: __device__ globals)
// ---------------------------------------------------------------------------
__device__ __half g_hQ[MM * EE];     // projected Q (prescaled by log2e/sqrt(S))
__device__ __half g_hK[MM * EE];
__device__ __half g_hV[MM * EE];
__device__ __half g_hC[MM * EE];     // attention context
__device__ __half g_hXq[MM * EE];    // fp16 copies of inputs
__device__ __half g_hXk[MM * EE];
__device__ __half g_hXv[MM * EE];
__device__ __half g_hWq[EE * EE];    // fp16 copies of weights
__device__ __half g_hWk[EE * EE];
__device__ __half g_hWv[EE * EE];
__device__ __half g_hWo[EE * EE];
__device__ __half g_hM[BB * SS];     // mask as fp16

// ---------------------------------------------------------------------------
// Helpers (baseline PTX only: sm_80-class mma/ldmatrix/cp.async)
// ---------------------------------------------------------------------------
__device__ __forceinline__ uint32_t smem_u32(const void* p) {
    uint32_t a;
    asm("{ .reg .u64 t; cvta.to.shared.u64 t, %1; cvt.u32.u64 %0, t; }"
        : "=r"(a) : "l"(p));
    return a;
}
__device__ __forceinline__ void ldsm4(uint32_t* r, uint32_t a) {
    asm volatile("ldmatrix.sync.aligned.m8n8.x4.shared.b16 {%0,%1,%2,%3}, [%4];"
        : "=r"(r[0]), "=r"(r[1]), "=r"(r[2]), "=r"(r[3]) : "r"(a));
}
__device__ __forceinline__ void ldsm4t(uint32_t* r, uint32_t a) {
    asm volatile("ldmatrix.sync.aligned.m8n8.x4.trans.shared.b16 {%0,%1,%2,%3}, [%4];"
        : "=r"(r[0]), "=r"(r[1]), "=r"(r[2]), "=r"(r[3]) : "r"(a));
}
// f32-accumulate HMMA
__device__ __forceinline__ void mma16816(float* c, const uint32_t* a, const uint32_t* b) {
    asm volatile("mma.sync.aligned.m16n8k16.row.col.f32.f16.f16.f32 "
        "{%0,%1,%2,%3}, {%4,%5,%6,%7}, {%8,%9}, {%0,%1,%2,%3};"
        : "+f"(c[0]), "+f"(c[1]), "+f"(c[2]), "+f"(c[3])
        : "r"(a[0]), "r"(a[1]), "r"(a[2]), "r"(a[3]), "r"(b[0]), "r"(b[1]));
}
// f16-accumulate HMMA (2x rate)
__device__ __forceinline__ void mma16816h(uint32_t* c, const uint32_t* a, const uint32_t* b) {
    asm volatile("mma.sync.aligned.m16n8k16.row.col.f16.f16.f16.f16 "
        "{%0,%1}, {%2,%3,%4,%5}, {%6,%7}, {%0,%1};"
        : "+r"(c[0]), "+r"(c[1])
        : "r"(a[0]), "r"(a[1]), "r"(a[2]), "r"(a[3]), "r"(b[0]), "r"(b[1]));
}
__device__ __forceinline__ uint32_t pack2(float x, float y) {
    __half2 h = __floats2half2_rn(x, y);
    return *reinterpret_cast<uint32_t*>(&h);
}
__device__ __forceinline__ uint32_t h2ex2(uint32_t x) {
    uint32_t y;
    asm("ex2.approx.f16x2 %0, %1;" : "=r"(y) : "r"(x));
    return y;
}
__device__ __forceinline__ uint32_t h2mul(uint32_t a, uint32_t b) {
    uint32_t y;
    asm("mul.f16x2 %0, %1, %2;" : "=r"(y) : "r"(a), "r"(b));
    return y;
}
__device__ __forceinline__ void cpa16(uint32_t s, const void* g) {
    asm volatile("cp.async.cg.shared.global [%0], [%1], 16;" :: "r"(s), "l"(g));
}
#define CP_COMMIT() asm volatile("cp.async.commit_group;" ::: "memory")
#define CP_WAIT0()  asm volatile("cp.async.wait_group 0;"  ::: "memory")
#define CP_WAIT2()  asm volatile("cp.async.wait_group 2;"  ::: "memory")

// Swizzles
__device__ __forceinline__ uint32_t sw64(int row, int ch) {
    return (uint32_t)(row * 64 + ((ch ^ ((row >> 1) & 3)) << 4));
}
__device__ __forceinline__ uint32_t sw128(int row, int ch) {
    uint32_t b = (uint32_t)(row * 128 + ch * 16);
    return b ^ ((b >> 3) & 0x70);
}
__device__ __forceinline__ uint32_t offA64(int rb, int cb, int lane) {
    int li = lane & 7, m = lane >> 3;
    return sw64(rb + li + (m & 1) * 8, cb + (m >> 1));
}
__device__ __forceinline__ uint32_t offB64(int rb, int cb, int lane) {
    int li = lane & 7, m = lane >> 3;
    return sw64(rb + (m >> 1) * 8 + li, cb + (m & 1));
}
__device__ __forceinline__ uint32_t offA128(int rb, int cb, int lane) {
    int li = lane & 7, m = lane >> 3;
    return sw128(rb + li + (m & 1) * 8, cb + (m >> 1));
}
__device__ __forceinline__ uint32_t offB128(int rb, int cb, int lane) {
    int li = lane & 7, m = lane >> 3;
    return sw128(rb + (m >> 1) * 8 + li, cb + (m & 1));
}

// ---------------------------------------------------------------------------
// Batched fp32 -> fp16 convert: 7 tensors + mask in ONE launch.
// ---------------------------------------------------------------------------
struct CvtArgs { const float4* s[7]; uint2* d[7]; const int4* ms; uint2* dM; };
#define ACT4 1048576
#define W4   262144
#define CVT_MAIN (3 * ACT4 + 4 * W4)

__global__ __launch_bounds__(256) void cvt_all(CvtArgs a)
{
    int i = blockIdx.x * 256 + threadIdx.x;
    if (i < CVT_MAIN) {
        int seg, off;
        if (i < 3 * ACT4) { seg = i >> 20;               off = i & (ACT4 - 1); }
        else              { int j = i - 3 * ACT4;
                            seg = 3 + (j >> 18);         off = j & (W4 - 1); }
        float4 v = a.s[seg][off];
        uint2 o;
        o.x = pack2(v.x, v.y);
        o.y = pack2(v.z, v.w);
        a.d[seg][off] = o;
    } else {
        int j = i - CVT_MAIN;                 // [0, 1024): mask int4 -> half x4
        int4 m = a.ms[j];
        uint2 o;
        o.x = pack2((float)m.x, (float)m.y);
        o.y = pack2((float)m.z, (float)m.w);
        a.dM[j] = o;
    }
}

// ---------------------------------------------------------------------------
// fp16 GEMM body — 4-stage cp.async pipeline, compile-time stage indices,
// one __syncthreads per k-block, fragment software pipelining. (R11 exact)
// ---------------------------------------------------------------------------
#define G_STAGE 16384u
#define G_SMEM  65536

template<bool OUT_HALF, bool HAS_BIAS>
__device__ __forceinline__ void gemm_body(
    const __half* __restrict__ A, const __half* __restrict__ B,
    const float* __restrict__ bias, void* __restrict__ Cout,
    int M, int N, float scale, char* smem)
{
    const int K = EE, NKB = 32;
    const int tid = threadIdx.x, lane = tid & 31, wid = tid >> 5;
    const int wm = wid & 3, wn = wid >> 2;
    const int bm = blockIdx.y * 128, bn = blockIdx.x * 128;

    const __half* Ag = A + (size_t)bm * K;
    const __half* Bg = B + (size_t)bn * K;
    const uint32_t sS = smem_u32(smem);

    float acc[2][8][4];
#pragma unroll
    for (int i = 0; i < 2; i++)
#pragma unroll
        for (int j = 0; j < 8; j++)
#pragma unroll
            for (int x = 0; x < 4; x++) acc[i][j][x] = 0.f;

    auto issue = [&](int kb, int st) {
        const uint32_t dA = sS + (uint32_t)st * G_STAGE;
#pragma unroll
        for (int i = 0; i < 2; i++) {
            int s = tid + 256 * i;
            int row = s >> 2, ch = s & 3;
            cpa16(dA + sw64(row, ch),         Ag + (size_t)row * K + kb * 32 + ch * 8);
            cpa16(dA + 8192u + sw64(row, ch), Bg + (size_t)row * K + kb * 32 + ch * 8);
        }
        CP_COMMIT();
    };

    issue(0, 0); issue(1, 1); issue(2, 2);

    auto kblock = [&](int kb, int st) {
        const uint32_t stA = sS + (uint32_t)st * G_STAGE;
        const uint32_t stB = stA + 8192u;
        CP_WAIT2();
        __syncthreads();

        uint32_t ac[2][4], an[2][4], bb[2][4];
        ldsm4(ac[0], stA + offA64(wm * 32,      0, lane));
        ldsm4(ac[1], stA + offA64(wm * 32 + 16, 0, lane));
        ldsm4(bb[0], stB + offB64(wn * 64, 0, lane));

        if (kb + 3 < NKB) issue(kb + 3, (kb + 3) & 3);
        else CP_COMMIT();   // empty group keeps wait_group 2 semantics uniform

#pragma unroll
        for (int kt = 0; kt < 2; kt++) {
#pragma unroll
            for (int np = 0; np < 4; np++) {
                const int nx = kt * 4 + np + 1;      // next fragment index
                if (nx < 8)
                    ldsm4(bb[(np + 1) & 1],
                          stB + offB64(wn * 64 + (nx & 3) * 16, (nx >> 2) * 2, lane));
                if (kt == 0 && np == 2)
                    ldsm4(an[0], stA + offA64(wm * 32,      2, lane));
                if (kt == 0 && np == 3)
                    ldsm4(an[1], stA + offA64(wm * 32 + 16, 2, lane));
                const uint32_t* a0 = kt ? an[0] : ac[0];
                const uint32_t* a1 = kt ? an[1] : ac[1];
                const uint32_t* bf = bb[np & 1];
                mma16816(acc[0][2 * np],     a0, bf);
                mma16816(acc[0][2 * np + 1], a0, bf + 2);
                mma16816(acc[1][2 * np],     a1, bf);
                mma16816(acc[1][2 * np + 1], a1, bf + 2);
            }
        }
    };

#pragma unroll 1
    for (int kb4 = 0; kb4 < NKB; kb4 += 4) {
        kblock(kb4 + 0, 0);
        kblock(kb4 + 1, 1);
        kblock(kb4 + 2, 2);
        kblock(kb4 + 3, 3);
    }

    const int g = lane >> 2, t = lane & 3;
#pragma unroll
    for (int mt = 0; mt < 2; mt++) {
        const int row0 = bm + wm * 32 + mt * 16 + g;
#pragma unroll
        for (int nt = 0; nt < 8; nt++) {
            const int col = bn + wn * 64 + nt * 8 + 2 * t;
            float* c = acc[mt][nt];
            if constexpr (OUT_HALF) {
                __half* O = (__half*)Cout;
                *(uint32_t*)(O + (size_t)row0 * N + col) =
                    pack2(c[0] * scale, c[1] * scale);
                *(uint32_t*)(O + (size_t)(row0 + 8) * N + col) =
                    pack2(c[2] * scale, c[3] * scale);
            } else {
                float* O = (float*)Cout;
                const float b0 = HAS_BIAS ? bias[col] : 0.f;
                const float b1 = HAS_BIAS ? bias[col + 1] : 0.f;
                *(float2*)(O + (size_t)row0 * N + col) =
                    make_float2(c[0] + b0, c[1] + b1);
                *(float2*)(O + (size_t)(row0 + 8) * N + col) =
                    make_float2(c[2] + b0, c[3] + b1);
            }
        }
    }
}

struct QkvArgs {
    const __half* A[3];
    const __half* B[3];
    __half*       C[3];
    float         scale[3];
};

__global__ __launch_bounds__(256, 2) void gemm_qkv(QkvArgs p)
{
    extern __shared__ __align__(16) char gsm[];
    const int z = blockIdx.z;
    gemm_body<true, false>(p.A[z], p.B[z], nullptr, p.C[z],
                           MM, EE, p.scale[z], gsm);
}

__global__ __launch_bounds__(256, 2) void gemm_out(
    const __half* __restrict__ A, const __half* __restrict__ B,
    const float* __restrict__ bias, float* __restrict__ C)
{
    extern __shared__ __align__(16) char gsm[];
    gemm_body<false, true>(A, B, bias, C, MM, EE, 1.0f, gsm);
}

// ---------------------------------------------------------------------------
// Flash attention v4.1 (R11 exact — measured local optimum):
// BQ=128 (4 warps x 32 q-rows), BKV=64, DH=64, 3 CTAs/SM.
//  - S = QK^T in fp16-accumulate HMMA; output lands in PV A-frag layout.
//  - joint q-block S loop (K frags shared), persistent Q fragments.
//  - f16x2 softmax in place; fp16 mask; ones-MMA row sums; PV f32-accum.
//  - single __syncthreads per tile.
// ---------------------------------------------------------------------------
#define F_OQ  0u
#define F_OK(i) (16384u + (i) * 8192u)
#define F_OV(i) (32768u + (i) * 8192u)
#define F_OMK   49152u
#define F_SMEM  (49152 + 2 * 128)

__global__ __launch_bounds__(128, 3) void flash4(
    const __half* __restrict__ Qh, const __half* __restrict__ Kh,
    const __half* __restrict__ Vh, const __half* __restrict__ Mh,
    __half* __restrict__ Oh)
{
    extern __shared__ __align__(16) char smraw[];
    const uint32_t S = smem_u32(smraw);

    const int tid = threadIdx.x, lane = tid & 31, w = tid >> 5;
    const int q0 = blockIdx.x * 128, h = blockIdx.y, b = blockIdx.z;
    const int g = lane >> 2, t = lane & 3;

    const __half* Qg = Qh + ((size_t)(b * SS + q0)) * EE + h * DHH;
    const __half* Kg = Kh + ((size_t)b * SS) * EE + h * DHH;
    const __half* Vg = Vh + ((size_t)b * SS) * EE + h * DHH;
    const __half* mgh = Mh + b * SS;

    auto issue_kv = [&](int kv0, int bi) {
#pragma unroll
        for (int i = 0; i < 4; i++) {
            int s = tid + 128 * i;
            int row = s >> 3, ch = s & 7;
            cpa16(S + F_OK(bi) + sw128(row, ch),
                  Kg + (size_t)(kv0 + row) * EE + ch * 8);
            cpa16(S + F_OV(bi) + sw128(row, ch),
                  Vg + (size_t)(kv0 + row) * EE + ch * 8);
        }
        if (tid < 8)
            cpa16(S + F_OMK + bi * 128 + tid * 16, mgh + kv0 + tid * 8);
        CP_COMMIT();
    };

    // prologue: Q tile + KV tile 0 in one group
#pragma unroll
    for (int i = 0; i < 8; i++) {
        int s = tid + 128 * i;
        int row = s >> 3, ch = s & 7;
        cpa16(S + F_OQ + sw128(row, ch), Qg + (size_t)row * EE + ch * 8);
    }
    issue_kv(0, 0);

    uint32_t aq[2][4][4];
    float acc[2][8][4];
    float lacc[2][4];
#pragma unroll
    for (int qb = 0; qb < 2; qb++) {
#pragma unroll
        for (int j = 0; j < 8; j++)
#pragma unroll
            for (int x = 0; x < 4; x++) acc[qb][j][x] = 0.f;
#pragma unroll
        for (int x = 0; x < 4; x++) lacc[qb][x] = 0.f;
    }
    const uint32_t ONES[2] = { 0x3C003C00u, 0x3C003C00u };  // half2(1,1)

    const int NT = SS / 64;
    for (int it = 0; it < NT; it++) {
        const int cur = it & 1;
        CP_WAIT0();
        __syncthreads();
        if (it == 0) {
#pragma unroll
            for (int qb = 0; qb < 2; qb++)
#pragma unroll
                for (int kt = 0; kt < 4; kt++)
                    ldsm4(aq[qb][kt], S + F_OQ + offA128(w * 32 + qb * 16, kt * 2, lane));
        }
        if (it + 1 < NT) issue_kv((it + 1) * 64, cur ^ 1);

        // ---- S = Q K^T, fp16 accumulate, joint q-blocks (K frag shared) ----
        uint32_t sh[2][8][2];
#pragma unroll
        for (int qb = 0; qb < 2; qb++)
#pragma unroll
            for (int j = 0; j < 8; j++) { sh[qb][j][0] = 0u; sh[qb][j][1] = 0u; }
#pragma unroll
        for (int kt = 0; kt < 4; kt++)
#pragma unroll
            for (int np = 0; np < 4; np++) {
                uint32_t bf[4];
                ldsm4(bf, S + F_OK(cur) + offB128(np * 16, kt * 2, lane));
                mma16816h(sh[0][2 * np],     aq[0][kt], bf);
                mma16816h(sh[0][2 * np + 1], aq[0][kt], bf + 2);
                mma16816h(sh[1][2 * np],     aq[1][kt], bf);
                mma16816h(sh[1][2 * np + 1], aq[1][kt], bf + 2);
            }

        // ---- P = exp2(S) * mask, f16x2, in place ----
#pragma unroll
        for (int j = 0; j < 8; j++) {
            const uint32_t mhj =
                *(const uint32_t*)(smraw + F_OMK + cur * 128 + (j * 8 + 2 * t) * 2);
            sh[0][j][0] = h2mul(h2ex2(sh[0][j][0]), mhj);
            sh[0][j][1] = h2mul(h2ex2(sh[0][j][1]), mhj);
            sh[1][j][0] = h2mul(h2ex2(sh[1][j][0]), mhj);
            sh[1][j][1] = h2mul(h2ex2(sh[1][j][1]), mhj);
        }

        // ---- O += P V (f32 accum) ; l += P * ones ----
#pragma unroll
        for (int kt = 0; kt < 4; kt++) {
            uint32_t ap0[4] = { sh[0][2 * kt][0], sh[0][2 * kt][1],
                                sh[0][2 * kt + 1][0], sh[0][2 * kt + 1][1] };
            uint32_t ap1[4] = { sh[1][2 * kt][0], sh[1][2 * kt][1],
                                sh[1][2 * kt + 1][0], sh[1][2 * kt + 1][1] };
            mma16816(lacc[0], ap0, ONES);
            mma16816(lacc[1], ap1, ONES);
#pragma unroll
            for (int np = 0; np < 4; np++) {
                uint32_t vf[4];
                ldsm4t(vf, S + F_OV(cur) + offA128(kt * 16, np * 2, lane));
                mma16816(acc[0][2 * np],     ap0, vf);
                mma16816(acc[0][2 * np + 1], ap0, vf + 2);
                mma16816(acc[1][2 * np],     ap1, vf);
                mma16816(acc[1][2 * np + 1], ap1, vf + 2);
            }
        }
        // no bottom sync: next iteration's top barrier provides ordering
    }

    // normalize and store
#pragma unroll
    for (int qb = 0; qb < 2; qb++) {
        const float i0 = 1.f / lacc[qb][0];
        const float i1 = 1.f / lacc[qb][2];
        __half* O0 = Oh + ((size_t)(b * SS + q0 + w * 32 + qb * 16 + g)) * EE + h * DHH;
        __half* O1 = O0 + 8 * EE;
#pragma unroll
        for (int j = 0; j < 8; j++) {
            const int col = j * 8 + 2 * t;
            *(uint32_t*)(O0 + col) = pack2(acc[qb][j][0] * i0, acc[qb][j][1] * i0);
            *(uint32_t*)(O1 + col) = pack2(acc[qb][j][2] * i1, acc[qb][j][3] * i1);
        }
    }
}

// ---------------------------------------------------------------------------
// Launch: 4 kernels total
// ---------------------------------------------------------------------------
extern "C" void kernel_launch(void* const* d_in, const int* in_sizes, int n_in,
                              void* d_out, int out_size)
{
    const float* q    = (const float*)d_in[0];
    const float* k    = (const float*)d_in[1];
    const float* v    = (const float*)d_in[2];
    const int*   mask = (const int*)d_in[3];
    const float* Wq   = (const float*)d_in[4];
    const float* Wk   = (const float*)d_in[5];
    const float* Wv   = (const float*)d_in[6];
    const float* Wo   = (const float*)d_in[7];
    const float* bo   = (const float*)d_in[8];
    float* out = (float*)d_out;

    __half *hQ, *hK, *hV, *hC, *hXq, *hXk, *hXv, *hWq, *hWk, *hWv, *hWo, *hM;
    cudaGetSymbolAddress((void**)&hQ,  g_hQ);
    cudaGetSymbolAddress((void**)&hK,  g_hK);
    cudaGetSymbolAddress((void**)&hV,  g_hV);
    cudaGetSymbolAddress((void**)&hC,  g_hC);
    cudaGetSymbolAddress((void**)&hXq, g_hXq);
    cudaGetSymbolAddress((void**)&hXk, g_hXk);
    cudaGetSymbolAddress((void**)&hXv, g_hXv);
    cudaGetSymbolAddress((void**)&hWq, g_hWq);
    cudaGetSymbolAddress((void**)&hWk, g_hWk);
    cudaGetSymbolAddress((void**)&hWv, g_hWv);
    cudaGetSymbolAddress((void**)&hWo, g_hWo);
    cudaGetSymbolAddress((void**)&hM,  g_hM);

    // 1) all fp32->fp16 converts (+ mask int->fp16) in one launch
    CvtArgs ca;
    ca.s[0] = (const float4*)q;  ca.d[0] = (uint2*)hXq;
    ca.s[1] = (const float4*)k;  ca.d[1] = (uint2*)hXk;
    ca.s[2] = (const float4*)v;  ca.d[2] = (uint2*)hXv;
    ca.s[3] = (const float4*)Wq; ca.d[3] = (uint2*)hWq;
    ca.s[4] = (const float4*)Wk; ca.d[4] = (uint2*)hWk;
    ca.s[5] = (const float4*)Wv; ca.d[5] = (uint2*)hWv;
    ca.s[6] = (const float4*)Wo; ca.d[6] = (uint2*)hWo;
    ca.ms = (const int4*)mask;   ca.dM = (uint2*)hM;
    cvt_all<<<CVT_MAIN / 256 + 4, 256>>>(ca);

    // 2) QKV projections, one launch (grid.z = 3), 4-stage pipelined GEMM
    cudaFuncSetAttribute(gemm_qkv, cudaFuncAttributeMaxDynamicSharedMemorySize,
                         G_SMEM);
    cudaFuncSetAttribute(gemm_out, cudaFuncAttributeMaxDynamicSharedMemorySize,
                         G_SMEM);
    QkvArgs pa;
    pa.A[0] = hXq; pa.B[0] = hWq; pa.C[0] = hQ; pa.scale[0] = 0.03188010863008193f;
    pa.A[1] = hXk; pa.B[1] = hWk; pa.C[1] = hK; pa.scale[1] = 1.0f;
    pa.A[2] = hXv; pa.B[2] = hWv; pa.C[2] = hV; pa.scale[2] = 1.0f;
    dim3 gqkv(EE / 128, MM / 128, 3);
    gemm_qkv<<<gqkv, 256, G_SMEM>>>(pa);

    // 3) attention (R11 flash4: BQ=128, 3 CTAs/SM)
    cudaFuncSetAttribute(flash4, cudaFuncAttributeMaxDynamicSharedMemorySize,
                         F_SMEM);
    flash4<<<dim3(SS / 128, HH, BB), 128, F_SMEM>>>(hQ, hK, hV, hM, hC);

    // 4) output projection + bias
    dim3 gg(EE / 128, MM / 128);
    gemm_out<<<gg, 256, G_SMEM>>>(hC, hWo, bo, out);
}

// round 15
// speedup vs baseline: 1.1449x; 1.0014x over previous
#include <cuda_runtime.h>
#include <cuda_fp16.h>
#include <math.h>
#include <cstdint>

// Problem constants
#define BB 2
#define SS 2048
#define EE 1024
#define HH 16
#define DHH 64
#define MM (BB * SS)   // 4096

// ---------------------------------------------------------------------------
// Scratch (allocation-free rule: __device__ globals)
// ---------------------------------------------------------------------------
__device__ __half g_hQ[MM * EE];     // projected Q (prescaled by log2e/sqrt(S))
__device__ __half g_hK[MM * EE];
__device__ __half g_hV[MM * EE];
__device__ __half g_hC[MM * EE];     // attention context
__device__ __half g_hXq[MM * EE];    // fp16 copies of inputs
__device__ __half g_hXk[MM * EE];
__device__ __half g_hXv[MM * EE];
__device__ __half g_hWq[EE * EE];    // fp16 copies of weights
__device__ __half g_hWk[EE * EE];
__device__ __half g_hWv[EE * EE];
__device__ __half g_hWo[EE * EE];
__device__ __half g_hM[BB * SS];     // mask as fp16

// ---------------------------------------------------------------------------
// Helpers (baseline PTX only: sm_80-class mma/ldmatrix/cp.async)
// ---------------------------------------------------------------------------
__device__ __forceinline__ uint32_t smem_u32(const void* p) {
    uint32_t a;
    asm("{ .reg .u64 t; cvta.to.shared.u64 t, %1; cvt.u32.u64 %0, t; }"
        : "=r"(a) : "l"(p));
    return a;
}
__device__ __forceinline__ void ldsm4(uint32_t* r, uint32_t a) {
    asm volatile("ldmatrix.sync.aligned.m8n8.x4.shared.b16 {%0,%1,%2,%3}, [%4];"
        : "=r"(r[0]), "=r"(r[1]), "=r"(r[2]), "=r"(r[3]) : "r"(a));
}
__device__ __forceinline__ void ldsm4t(uint32_t* r, uint32_t a) {
    asm volatile("ldmatrix.sync.aligned.m8n8.x4.trans.shared.b16 {%0,%1,%2,%3}, [%4];"
        : "=r"(r[0]), "=r"(r[1]), "=r"(r[2]), "=r"(r[3]) : "r"(a));
}
// f32-accumulate HMMA
__device__ __forceinline__ void mma16816(float* c, const uint32_t* a, const uint32_t* b) {
    asm volatile("mma.sync.aligned.m16n8k16.row.col.f32.f16.f16.f32 "
        "{%0,%1,%2,%3}, {%4,%5,%6,%7}, {%8,%9}, {%0,%1,%2,%3};"
        : "+f"(c[0]), "+f"(c[1]), "+f"(c[2]), "+f"(c[3])
        : "r"(a[0]), "r"(a[1]), "r"(a[2]), "r"(a[3]), "r"(b[0]), "r"(b[1]));
}
// f16-accumulate HMMA (2x rate)
__device__ __forceinline__ void mma16816h(uint32_t* c, const uint32_t* a, const uint32_t* b) {
    asm volatile("mma.sync.aligned.m16n8k16.row.col.f16.f16.f16.f16 "
        "{%0,%1}, {%2,%3,%4,%5}, {%6,%7}, {%0,%1};"
        : "+r"(c[0]), "+r"(c[1])
        : "r"(a[0]), "r"(a[1]), "r"(a[2]), "r"(a[3]), "r"(b[0]), "r"(b[1]));
}
__device__ __forceinline__ uint32_t pack2(float x, float y) {
    __half2 h = __floats2half2_rn(x, y);
    return *reinterpret_cast<uint32_t*>(&h);
}
__device__ __forceinline__ uint32_t h2ex2(uint32_t x) {
    uint32_t y;
    asm("ex2.approx.f16x2 %0, %1;" : "=r"(y) : "r"(x));
    return y;
}
__device__ __forceinline__ uint32_t h2mul(uint32_t a, uint32_t b) {
    uint32_t y;
    asm("mul.f16x2 %0, %1, %2;" : "=r"(y) : "r"(a), "r"(b));
    return y;
}
__device__ __forceinline__ void cpa16(uint32_t s, const void* g) {
    asm volatile("cp.async.cg.shared.global [%0], [%1], 16;" :: "r"(s), "l"(g));
}
#define CP_COMMIT() asm volatile("cp.async.commit_group;" ::: "memory")
#define CP_WAIT0()  asm volatile("cp.async.wait_group 0;"  ::: "memory")
#define CP_WAIT1()  asm volatile("cp.async.wait_group 1;"  ::: "memory")
#define CP_WAIT2()  asm volatile("cp.async.wait_group 2;"  ::: "memory")

// Swizzles
__device__ __forceinline__ uint32_t sw64(int row, int ch) {
    return (uint32_t)(row * 64 + ((ch ^ ((row >> 1) & 3)) << 4));
}
__device__ __forceinline__ uint32_t sw128(int row, int ch) {
    uint32_t b = (uint32_t)(row * 128 + ch * 16);
    return b ^ ((b >> 3) & 0x70);
}
__device__ __forceinline__ uint32_t offA64(int rb, int cb, int lane) {
    int li = lane & 7, m = lane >> 3;
    return sw64(rb + li + (m & 1) * 8, cb + (m >> 1));
}
__device__ __forceinline__ uint32_t offB64(int rb, int cb, int lane) {
    int li = lane & 7, m = lane >> 3;
    return sw64(rb + (m >> 1) * 8 + li, cb + (m & 1));
}
__device__ __forceinline__ uint32_t offA128(int rb, int cb, int lane) {
    int li = lane & 7, m = lane >> 3;
    return sw128(rb + li + (m & 1) * 8, cb + (m >> 1));
}
__device__ __forceinline__ uint32_t offB128(int rb, int cb, int lane) {
    int li = lane & 7, m = lane >> 3;
    return sw128(rb + (m >> 1) * 8 + li, cb + (m & 1));
}

// ---------------------------------------------------------------------------
// Batched fp32 -> fp16 convert: 7 tensors + mask in ONE launch.
// ---------------------------------------------------------------------------
struct CvtArgs { const float4* s[7]; uint2* d[7]; const int4* ms; uint2* dM; };
#define ACT4 1048576
#define W4   262144
#define CVT_MAIN (3 * ACT4 + 4 * W4)

__global__ __launch_bounds__(256) void cvt_all(CvtArgs a)
{
    int i = blockIdx.x * 256 + threadIdx.x;
    if (i < CVT_MAIN) {
        int seg, off;
        if (i < 3 * ACT4) { seg = i >> 20;               off = i & (ACT4 - 1); }
        else              { int j = i - 3 * ACT4;
                            seg = 3 + (j >> 18);         off = j & (W4 - 1); }
        float4 v = a.s[seg][off];
        uint2 o;
        o.x = pack2(v.x, v.y);
        o.y = pack2(v.z, v.w);
        a.d[seg][off] = o;
    } else {
        int j = i - CVT_MAIN;                 // [0, 1024): mask int4 -> half x4
        int4 m = a.ms[j];
        uint2 o;
        o.x = pack2((float)m.x, (float)m.y);
        o.y = pack2((float)m.z, (float)m.w);
        a.dM[j] = o;
    }
}

// ---------------------------------------------------------------------------
// fp16 GEMM body — 4-stage cp.async pipeline (R11/R14 exact, proven).
// ---------------------------------------------------------------------------
#define G_STAGE 16384u
#define G_SMEM  65536

template<bool OUT_HALF, bool HAS_BIAS>
__device__ __forceinline__ void gemm_body(
    const __half* __restrict__ A, const __half* __restrict__ B,
    const float* __restrict__ bias, void* __restrict__ Cout,
    int M, int N, float scale, char* smem)
{
    const int K = EE, NKB = 32;
    const int tid = threadIdx.x, lane = tid & 31, wid = tid >> 5;
    const int wm = wid & 3, wn = wid >> 2;
    const int bm = blockIdx.y * 128, bn = blockIdx.x * 128;

    const __half* Ag = A + (size_t)bm * K;
    const __half* Bg = B + (size_t)bn * K;
    const uint32_t sS = smem_u32(smem);

    float acc[2][8][4];
#pragma unroll
    for (int i = 0; i < 2; i++)
#pragma unroll
        for (int j = 0; j < 8; j++)
#pragma unroll
            for (int x = 0; x < 4; x++) acc[i][j][x] = 0.f;

    auto issue = [&](int kb, int st) {
        const uint32_t dA = sS + (uint32_t)st * G_STAGE;
#pragma unroll
        for (int i = 0; i < 2; i++) {
            int s = tid + 256 * i;
            int row = s >> 2, ch = s & 3;
            cpa16(dA + sw64(row, ch),         Ag + (size_t)row * K + kb * 32 + ch * 8);
            cpa16(dA + 8192u + sw64(row, ch), Bg + (size_t)row * K + kb * 32 + ch * 8);
        }
        CP_COMMIT();
    };

    issue(0, 0); issue(1, 1); issue(2, 2);

    auto kblock = [&](int kb, int st) {
        const uint32_t stA = sS + (uint32_t)st * G_STAGE;
        const uint32_t stB = stA + 8192u;
        CP_WAIT2();
        __syncthreads();

        uint32_t ac[2][4], an[2][4], bb[2][4];
        ldsm4(ac[0], stA + offA64(wm * 32,      0, lane));
        ldsm4(ac[1], stA + offA64(wm * 32 + 16, 0, lane));
        ldsm4(bb[0], stB + offB64(wn * 64, 0, lane));

        if (kb + 3 < NKB) issue(kb + 3, (kb + 3) & 3);
        else CP_COMMIT();   // empty group keeps wait_group 2 semantics uniform

#pragma unroll
        for (int kt = 0; kt < 2; kt++) {
#pragma unroll
            for (int np = 0; np < 4; np++) {
                const int nx = kt * 4 + np + 1;      // next fragment index
                if (nx < 8)
                    ldsm4(bb[(np + 1) & 1],
                          stB + offB64(wn * 64 + (nx & 3) * 16, (nx >> 2) * 2, lane));
                if (kt == 0 && np == 2)
                    ldsm4(an[0], stA + offA64(wm * 32,      2, lane));
                if (kt == 0 && np == 3)
                    ldsm4(an[1], stA + offA64(wm * 32 + 16, 2, lane));
                const uint32_t* a0 = kt ? an[0] : ac[0];
                const uint32_t* a1 = kt ? an[1] : ac[1];
                const uint32_t* bf = bb[np & 1];
                mma16816(acc[0][2 * np],     a0, bf);
                mma16816(acc[0][2 * np + 1], a0, bf + 2);
                mma16816(acc[1][2 * np],     a1, bf);
                mma16816(acc[1][2 * np + 1], a1, bf + 2);
            }
        }
    };

#pragma unroll 1
    for (int kb4 = 0; kb4 < NKB; kb4 += 4) {
        kblock(kb4 + 0, 0);
        kblock(kb4 + 1, 1);
        kblock(kb4 + 2, 2);
        kblock(kb4 + 3, 3);
    }

    const int g = lane >> 2, t = lane & 3;
#pragma unroll
    for (int mt = 0; mt < 2; mt++) {
        const int row0 = bm + wm * 32 + mt * 16 + g;
#pragma unroll
        for (int nt = 0; nt < 8; nt++) {
            const int col = bn + wn * 64 + nt * 8 + 2 * t;
            float* c = acc[mt][nt];
            if constexpr (OUT_HALF) {
                __half* O = (__half*)Cout;
                *(uint32_t*)(O + (size_t)row0 * N + col) =
                    pack2(c[0] * scale, c[1] * scale);
                *(uint32_t*)(O + (size_t)(row0 + 8) * N + col) =
                    pack2(c[2] * scale, c[3] * scale);
            } else {
                float* O = (float*)Cout;
                const float b0 = HAS_BIAS ? bias[col] : 0.f;
                const float b1 = HAS_BIAS ? bias[col + 1] : 0.f;
                *(float2*)(O + (size_t)row0 * N + col) =
                    make_float2(c[0] + b0, c[1] + b1);
                *(float2*)(O + (size_t)(row0 + 8) * N + col) =
                    make_float2(c[2] + b0, c[3] + b1);
            }
        }
    }
}

struct QkvArgs {
    const __half* A[3];
    const __half* B[3];
    __half*       C[3];
    float         scale[3];
};

__global__ __launch_bounds__(256, 2) void gemm_qkv(QkvArgs p)
{
    extern __shared__ __align__(16) char gsm[];
    const int z = blockIdx.z;
    gemm_body<true, false>(p.A[z], p.B[z], nullptr, p.C[z],
                           MM, EE, p.scale[z], gsm);
}

__global__ __launch_bounds__(256, 2) void gemm_out(
    const __half* __restrict__ A, const __half* __restrict__ B,
    const float* __restrict__ bias, float* __restrict__ C)
{
    extern __shared__ __align__(16) char gsm[];
    gemm_body<false, true>(A, B, bias, C, MM, EE, 1.0f, gsm);
}

// ---------------------------------------------------------------------------
// Flash attention v8: R14's flash4 warp body + 3-buffer KV ring with
// wait_group 1 (2-tile load lookahead). Buffer index = cheap cycling regs,
// bases hoisted per iteration; empty commits keep group counting uniform.
// smem: Q 16K | KV ring 3 x (K 8K + V 8K) | mask 3 x 128B  = 65.9 KB
// 3 CTAs/SM (197.8 KB).
// ---------------------------------------------------------------------------
#define F_OQ  0u
#define F_OK3(i) (16384u + (uint32_t)(i) * 16384u)
#define F_OV3(i) (24576u + (uint32_t)(i) * 16384u)
#define F_OMK3   65536u
#define F_SMEM3  (65536 + 3 * 128)

__global__ __launch_bounds__(128, 3) void flash8(
    const __half* __restrict__ Qh, const __half* __restrict__ Kh,
    const __half* __restrict__ Vh, const __half* __restrict__ Mh,
    __half* __restrict__ Oh)
{
    extern __shared__ __align__(16) char smraw[];
    const uint32_t S = smem_u32(smraw);

    const int tid = threadIdx.x, lane = tid & 31, w = tid >> 5;
    const int q0 = blockIdx.x * 128, h = blockIdx.y, b = blockIdx.z;
    const int g = lane >> 2, t = lane & 3;

    const __half* Qg = Qh + ((size_t)(b * SS + q0)) * EE + h * DHH;
    const __half* Kg = Kh + ((size_t)b * SS) * EE + h * DHH;
    const __half* Vg = Vh + ((size_t)b * SS) * EE + h * DHH;
    const __half* mgh = Mh + b * SS;

    auto issue_kv = [&](int kv0, int bi) {
#pragma unroll
        for (int i = 0; i < 4; i++) {
            int s = tid + 128 * i;
            int row = s >> 3, ch = s & 7;
            cpa16(S + F_OK3(bi) + sw128(row, ch),
                  Kg + (size_t)(kv0 + row) * EE + ch * 8);
            cpa16(S + F_OV3(bi) + sw128(row, ch),
                  Vg + (size_t)(kv0 + row) * EE + ch * 8);
        }
        if (tid < 8)
            cpa16(S + F_OMK3 + (uint32_t)bi * 128 + tid * 16, mgh + kv0 + tid * 8);
        CP_COMMIT();
    };

    // prologue: group1 = Q tile + KV tile 0; group2 = KV tile 1
#pragma unroll
    for (int i = 0; i < 8; i++) {
        int s = tid + 128 * i;
        int row = s >> 3, ch = s & 7;
        cpa16(S + F_OQ + sw128(row, ch), Qg + (size_t)row * EE + ch * 8);
    }
    issue_kv(0, 0);
    issue_kv(64, 1);

    uint32_t aq[2][4][4];
    float acc[2][8][4];
    float lacc[2][4];
#pragma unroll
    for (int qb = 0; qb < 2; qb++) {
#pragma unroll
        for (int j = 0; j < 8; j++)
#pragma unroll
            for (int x = 0; x < 4; x++) acc[qb][j][x] = 0.f;
#pragma unroll
        for (int x = 0; x < 4; x++) lacc[qb][x] = 0.f;
    }
    const uint32_t ONES[2] = { 0x3C003C00u, 0x3C003C00u };  // half2(1,1)

    const int NT = SS / 64;
    int st = 0;        // buffer of tile `it`
    int st2 = 2;       // buffer of tile `it+2`
    for (int it = 0; it < NT; it++) {
        CP_WAIT1();    // tile `it` complete; tile `it+1` may be in flight
        __syncthreads();
        if (it == 0) {
#pragma unroll
            for (int qb = 0; qb < 2; qb++)
#pragma unroll
                for (int kt = 0; kt < 4; kt++)
                    ldsm4(aq[qb][kt], S + F_OQ + offA128(w * 32 + qb * 16, kt * 2, lane));
        }
        if (it + 2 < NT) issue_kv((it + 2) * 64, st2);
        else CP_COMMIT();   // uniform group counting

        const uint32_t bK = S + F_OK3(st);
        const uint32_t bV = S + F_OV3(st);
        const uint32_t bM = (uint32_t)st * 128u;

        // ---- S = Q K^T, fp16 accumulate, joint q-blocks (K frag shared) ----
        uint32_t sh[2][8][2];
#pragma unroll
        for (int qb = 0; qb < 2; qb++)
#pragma unroll
            for (int j = 0; j < 8; j++) { sh[qb][j][0] = 0u; sh[qb][j][1] = 0u; }
#pragma unroll
        for (int kt = 0; kt < 4; kt++)
#pragma unroll
            for (int np = 0; np < 4; np++) {
                uint32_t bf[4];
                ldsm4(bf, bK + offB128(np * 16, kt * 2, lane));
                mma16816h(sh[0][2 * np],     aq[0][kt], bf);
                mma16816h(sh[0][2 * np + 1], aq[0][kt], bf + 2);
                mma16816h(sh[1][2 * np],     aq[1][kt], bf);
                mma16816h(sh[1][2 * np + 1], aq[1][kt], bf + 2);
            }

        // ---- P = exp2(S) * mask, f16x2, in place ----
#pragma unroll
        for (int j = 0; j < 8; j++) {
            const uint32_t mhj =
                *(const uint32_t*)(smraw + F_OMK3 + bM + (j * 8 + 2 * t) * 2);
            sh[0][j][0] = h2mul(h2ex2(sh[0][j][0]), mhj);
            sh[0][j][1] = h2mul(h2ex2(sh[0][j][1]), mhj);
            sh[1][j][0] = h2mul(h2ex2(sh[1][j][0]), mhj);
            sh[1][j][1] = h2mul(h2ex2(sh[1][j][1]), mhj);
        }

        // ---- O += P V (f32 accum) ; l += P * ones ----
#pragma unroll
        for (int kt = 0; kt < 4; kt++) {
            uint32_t ap0[4] = { sh[0][2 * kt][0], sh[0][2 * kt][1],
                                sh[0][2 * kt + 1][0], sh[0][2 * kt + 1][1] };
            uint32_t ap1[4] = { sh[1][2 * kt][0], sh[1][2 * kt][1],
                                sh[1][2 * kt + 1][0], sh[1][2 * kt + 1][1] };
            mma16816(lacc[0], ap0, ONES);
            mma16816(lacc[1], ap1, ONES);
#pragma unroll
            for (int np = 0; np < 4; np++) {
                uint32_t vf[4];
                ldsm4t(vf, bV + offA128(kt * 16, np * 2, lane));
                mma16816(acc[0][2 * np],     ap0, vf);
                mma16816(acc[0][2 * np + 1], ap0, vf + 2);
                mma16816(acc[1][2 * np],     ap1, vf);
                mma16816(acc[1][2 * np + 1], ap1, vf + 2);
            }
        }

        st  = (st  == 2) ? 0 : st  + 1;
        st2 = (st2 == 2) ? 0 : st2 + 1;
        // no bottom sync: next iteration's top barrier provides ordering
    }

    // normalize and store
#pragma unroll
    for (int qb = 0; qb < 2; qb++) {
        const float i0 = 1.f / lacc[qb][0];
        const float i1 = 1.f / lacc[qb][2];
        __half* O0 = Oh + ((size_t)(b * SS + q0 + w * 32 + qb * 16 + g)) * EE + h * DHH;
        __half* O1 = O0 + 8 * EE;
#pragma unroll
        for (int j = 0; j < 8; j++) {
            const int col = j * 8 + 2 * t;
            *(uint32_t*)(O0 + col) = pack2(acc[qb][j][0] * i0, acc[qb][j][1] * i0);
            *(uint32_t*)(O1 + col) = pack2(acc[qb][j][2] * i1, acc[qb][j][3] * i1);
        }
    }
}

// ---------------------------------------------------------------------------
// Launch: 4 kernels total
// ---------------------------------------------------------------------------
extern "C" void kernel_launch(void* const* d_in, const int* in_sizes, int n_in,
                              void* d_out, int out_size)
{
    const float* q    = (const float*)d_in[0];
    const float* k    = (const float*)d_in[1];
    const float* v    = (const float*)d_in[2];
    const int*   mask = (const int*)d_in[3];
    const float* Wq   = (const float*)d_in[4];
    const float* Wk   = (const float*)d_in[5];
    const float* Wv   = (const float*)d_in[6];
    const float* Wo   = (const float*)d_in[7];
    const float* bo   = (const float*)d_in[8];
    float* out = (float*)d_out;

    __half *hQ, *hK, *hV, *hC, *hXq, *hXk, *hXv, *hWq, *hWk, *hWv, *hWo, *hM;
    cudaGetSymbolAddress((void**)&hQ,  g_hQ);
    cudaGetSymbolAddress((void**)&hK,  g_hK);
    cudaGetSymbolAddress((void**)&hV,  g_hV);
    cudaGetSymbolAddress((void**)&hC,  g_hC);
    cudaGetSymbolAddress((void**)&hXq, g_hXq);
    cudaGetSymbolAddress((void**)&hXk, g_hXk);
    cudaGetSymbolAddress((void**)&hXv, g_hXv);
    cudaGetSymbolAddress((void**)&hWq, g_hWq);
    cudaGetSymbolAddress((void**)&hWk, g_hWk);
    cudaGetSymbolAddress((void**)&hWv, g_hWv);
    cudaGetSymbolAddress((void**)&hWo, g_hWo);
    cudaGetSymbolAddress((void**)&hM,  g_hM);

    // 1) all fp32->fp16 converts (+ mask int->fp16) in one launch
    CvtArgs ca;
    ca.s[0] = (const float4*)q;  ca.d[0] = (uint2*)hXq;
    ca.s[1] = (const float4*)k;  ca.d[1] = (uint2*)hXk;
    ca.s[2] = (const float4*)v;  ca.d[2] = (uint2*)hXv;
    ca.s[3] = (const float4*)Wq; ca.d[3] = (uint2*)hWq;
    ca.s[4] = (const float4*)Wk; ca.d[4] = (uint2*)hWk;
    ca.s[5] = (const float4*)Wv; ca.d[5] = (uint2*)hWv;
    ca.s[6] = (const float4*)Wo; ca.d[6] = (uint2*)hWo;
    ca.ms = (const int4*)mask;   ca.dM = (uint2*)hM;
    cvt_all<<<CVT_MAIN / 256 + 4, 256>>>(ca);

    // 2) QKV projections, one launch (grid.z = 3), 4-stage pipelined GEMM
    cudaFuncSetAttribute(gemm_qkv, cudaFuncAttributeMaxDynamicSharedMemorySize,
                         G_SMEM);
    cudaFuncSetAttribute(gemm_out, cudaFuncAttributeMaxDynamicSharedMemorySize,
                         G_SMEM);
    QkvArgs pa;
    pa.A[0] = hXq; pa.B[0] = hWq; pa.C[0] = hQ; pa.scale[0] = 0.03188010863008193f;
    pa.A[1] = hXk; pa.B[1] = hWk; pa.C[1] = hK; pa.scale[1] = 1.0f;
    pa.A[2] = hXv; pa.B[2] = hWv; pa.C[2] = hV; pa.scale[2] = 1.0f;
    dim3 gqkv(EE / 128, MM / 128, 3);
    gemm_qkv<<<gqkv, 256, G_SMEM>>>(pa);

    // 3) attention (flash8: 3-buffer KV ring, 2-tile lookahead)
    cudaFuncSetAttribute(flash8, cudaFuncAttributeMaxDynamicSharedMemorySize,
                         F_SMEM3);
    flash8<<<dim3(SS / 128, HH, BB), 128, F_SMEM3>>>(hQ, hK, hV, hM, hC);

    // 4) output projection + bias
    dim3 gg(EE / 128, MM / 128);
    gemm_out<<<gg, 256, G_SMEM>>>(hC, hWo, bo, out);
}